// round 3
// baseline (speedup 1.0000x reference)
#include <cuda_runtime.h>

#define NB 8
#define NS 4
#define NHY 50
#define NV 200
#define NE 400
#define NL 2
#define FD 79
#define HD 128
#define WN1R 207
#define NNODE (NB*NS*NHY)

// ------------- device scratch (no allocation) -------------
__device__ float g_cA [NNODE*HD];
__device__ float g_cBh[NNODE*HD];
__device__ float g_cBv[NB*NV*HD];
__device__ float g_feat[NNODE*FD];
__device__ float g_x   [NNODE*3];
__device__ float g_aggm[NNODE*HD];
__device__ float g_aggx[NNODE*3];
__device__ int   g_start[NB*(NHY+1)];
__device__ int   g_col[NB*NE];
__device__ float g_em [NB*NE];

__device__ __forceinline__ float silu_f(float x) {
    return __fdividef(x, 1.0f + __expf(-x));
}

// ------------- CSR of h-h edges, deterministic -------------
__global__ void csr_k(const int* __restrict__ e, const float* __restrict__ em) {
    __shared__ int cnt[NHY+1];
    int b = blockIdx.x, t = threadIdx.x;
    if (t <= NHY) cnt[t] = 0;
    __syncthreads();
    if (t < NHY) {
        int c = 0;
        for (int i = 0; i < NE; i++) if (e[(b*NE+i)*2] == t) c++;
        cnt[t+1] = c;
    }
    __syncthreads();
    if (t == 0) for (int i = 0; i < NHY; i++) cnt[i+1] += cnt[i];
    __syncthreads();
    if (t <= NHY) g_start[b*(NHY+1)+t] = cnt[t];
    if (t < NHY) {
        int p = cnt[t];
        for (int i = 0; i < NE; i++) if (e[(b*NE+i)*2] == t) {
            g_col[b*NE+p] = e[(b*NE+i)*2+1];
            g_em [b*NE+p] = em[b*NE+i];
            p++;
        }
    }
}

// ------------- init: abs positions + one-hot h features -------------
__global__ void init_k(const float* __restrict__ x_h, const float* __restrict__ x_hv,
                       const int* __restrict__ bound, const int* __restrict__ labh,
                       const int* __restrict__ posh, const int* __restrict__ pept) {
    int idx = blockIdx.x*blockDim.x + threadIdx.x;
    if (idx >= NNODE) return;
    int r = idx % NHY;
    int b = idx / (NHY*NS);
    int ba = bound[b*NHY+r];
    for (int c = 0; c < 3; ++c)
        g_x[idx*3+c] = x_h[idx*3+c] + x_hv[(b*NV+ba)*3+c];
    int lab = labh[b*NHY+r], pos = posh[b*NHY+r];
    int aa = pept[b*15 + pos - 1];
    float* f = g_feat + idx*FD;
    for (int i = 0; i < FD; ++i) f[i] = 0.f;
    f[lab] = 1.f; f[44+aa] = 1.f; f[64+pos-1] = 1.f;
}

// ------------- per layer: heavy cB via one-hot gathers -------------
__global__ void heavycb_k(int l, const float* __restrict__ W1,
                          const int* __restrict__ labv, const int* __restrict__ posv,
                          const int* __restrict__ pept) {
    int idx = blockIdx.x*blockDim.x + threadIdx.x;
    if (idx >= NB*NV*HD) return;
    int k = idx % HD;
    int j = (idx / HD) % NV;
    int b = idx / (HD*NV);
    int lab = labv[b*NV+j];
    int pos = posv[b*NV+j];
    int aa  = pept[b*15 + pos - 1];
    const float* W = W1 + l*161*HD;
    g_cBv[idx] = W[(FD+lab)*HD+k] + W[(FD+44+aa)*HD+k] + W[(FD+64+pos-1)*HD+k];
}

// ------------- per layer: h-node cA (b1+t folded) and cB -------------
__global__ void hcab_k(int l, const float* __restrict__ W1,
                       const float* __restrict__ b1, const float* __restrict__ t) {
    __shared__ float fs[FD];
    int nidx = blockIdx.x;
    int b = nidx / (NHY*NS);
    int tid = threadIdx.x;
    if (tid < FD) fs[tid] = g_feat[nidx*FD+tid];
    __syncthreads();
    const float* W = W1 + l*161*HD;
    float a  = b1[l*HD+tid] + t[b]*W[160*HD+tid];
    float bb = 0.f;
    #pragma unroll 4
    for (int f = 0; f < FD; ++f) {
        float fv = fs[f];
        a  = fmaf(fv, W[f*HD+tid], a);
        bb = fmaf(fv, W[(FD+f)*HD+tid], bb);
    }
    g_cA [nidx*HD+tid] = a;
    g_cBh[nidx*HD+tid] = bb;
}

// ------------- shared GEMM: 4 edges x 4 cols per thread, K=128 -------------
__device__ __forceinline__ void gemm4x4(const float* __restrict__ A, int eg,
                                        const float* __restrict__ Ws, int c,
                                        float acc[16]) {
    #pragma unroll 4
    for (int j = 0; j < HD; j += 4) {
        float4 w0 = *(const float4*)(Ws + (j+0)*HD + c);
        float4 w1 = *(const float4*)(Ws + (j+1)*HD + c);
        float4 w2 = *(const float4*)(Ws + (j+2)*HD + c);
        float4 w3 = *(const float4*)(Ws + (j+3)*HD + c);
        #pragma unroll
        for (int u = 0; u < 4; ++u) {
            float4 a = *(const float4*)(A + (eg + u*8)*132 + j);
            float* ac = acc + u*4;
            ac[0]=fmaf(a.x,w0.x,ac[0]); ac[1]=fmaf(a.x,w0.y,ac[1]); ac[2]=fmaf(a.x,w0.z,ac[2]); ac[3]=fmaf(a.x,w0.w,ac[3]);
            ac[0]=fmaf(a.y,w1.x,ac[0]); ac[1]=fmaf(a.y,w1.y,ac[1]); ac[2]=fmaf(a.y,w1.z,ac[2]); ac[3]=fmaf(a.y,w1.w,ac[3]);
            ac[0]=fmaf(a.z,w2.x,ac[0]); ac[1]=fmaf(a.z,w2.y,ac[1]); ac[2]=fmaf(a.z,w2.z,ac[2]); ac[3]=fmaf(a.z,w2.w,ac[3]);
            ac[0]=fmaf(a.w,w3.x,ac[0]); ac[1]=fmaf(a.w,w3.y,ac[1]); ac[2]=fmaf(a.w,w3.z,ac[2]); ac[3]=fmaf(a.w,w3.w,ac[3]);
        }
    }
}

#define EDGE_SMEM_BYTES (43400*4)

// ------------- edge kernel: 1 block per (b,s,row) -------------
__global__ void __launch_bounds__(256, 1)
edge_k(int l,
       const float* __restrict__ W1,  const float* __restrict__ W2g,
       const float* __restrict__ b2g, const float* __restrict__ Wc1g,
       const float* __restrict__ bc1g,const float* __restrict__ Wc2g,
       const float* __restrict__ x_hv,const float* __restrict__ bondm,
       const float* __restrict__ emhv) {
    extern __shared__ float es[];
    float* W2s   = es;                  // 16384
    float* Wc1s  = es + 16384;          // 16384
    float* b2s   = es + 32768;          // 128
    float* bc1s  = b2s  + HD;           // 128
    float* wc2s  = bc1s + HD;           // 128
    float* w1d   = wc2s + HD;           // 128
    float* w1b   = w1d  + HD;           // 128
    float* cAs   = w1b  + HD;           // 128
    float* m1s   = cAs  + HD;           // 32*132 = 4224
    float* m2s   = m1s  + 32*132;       // 4224
    float* aggm  = m2s  + 32*132;       // 128
    float* cwp   = aggm + HD;           // 32*32 = 1024
    float* diffs = cwp  + 1024;         // 96
    float* dists = diffs+ 96;           // 32
    float* bonds = dists+ 32;           // 32
    float* ems   = bonds+ 32;           // 32
    float* cws   = ems  + 32;           // 32
    float* xrs   = cws  + 32;           // 4
    float* aggx  = xrs  + 4;            // 4
    int*   colss = (int*)(aggx + 4);    // 32

    int tid = threadIdx.x;
    int blk = blockIdx.x;
    int r = blk % NHY;
    int s = (blk / NHY) % NS;
    int b = blk / (NHY*NS);
    int nidx = (b*NS+s)*NHY + r;

    const float* W2p  = W2g  + l*HD*HD;
    const float* Wc1p = Wc1g + l*HD*HD;
    for (int i = tid; i < HD*HD/4; i += 256) {
        ((float4*)W2s)[i]  = ((const float4*)W2p)[i];
        ((float4*)Wc1s)[i] = ((const float4*)Wc1p)[i];
    }
    if (tid < HD) {
        b2s [tid] = b2g [l*HD+tid];
        bc1s[tid] = bc1g[l*HD+tid];
        wc2s[tid] = Wc2g[l*HD+tid];
        w1d [tid] = W1[(l*161+158)*HD+tid];
        w1b [tid] = W1[(l*161+159)*HD+tid];
        cAs [tid] = g_cA[nidx*HD+tid];
        aggm[tid] = 0.f;
    }
    if (tid < 3) { xrs[tid] = g_x[nidx*3+tid]; aggx[tid] = 0.f; }
    int hh0   = g_start[b*(NHY+1)+r];
    int hhcnt = g_start[b*(NHY+1)+r+1] - hh0;
    int ne = NV + hhcnt;
    int ntile = (ne + 31) >> 5;
    __syncthreads();

    for (int tile = 0; tile < ntile; ++tile) {
        // --- stage 0: per-edge scalars ---
        if (tid < 32) {
            int e = tile*32 + tid;
            int col = NHY; float bond = 0.f, em = 0.f;
            float d0 = 0.f, d1 = 0.f, d2 = 0.f;
            if (e < NV) {
                col  = NHY + e;
                bond = bondm[(b*NHY+r)*NV + e];
                em   = emhv [(b*NHY+r)*NV + e];
            } else if (e < ne) {
                int ii = hh0 + (e - NV);
                col = g_col[b*NE+ii];
                em  = g_em [b*NE+ii];
            }
            if (e < ne) {
                const float* xc = (col >= NHY) ? (x_hv + (b*NV + (col-NHY))*3)
                                               : (g_x + ((b*NS+s)*NHY+col)*3);
                d0 = xrs[0]-xc[0]; d1 = xrs[1]-xc[1]; d2 = xrs[2]-xc[2];
            }
            diffs[tid*3+0]=d0; diffs[tid*3+1]=d1; diffs[tid*3+2]=d2;
            dists[tid] = sqrtf(d0*d0 + d1*d1 + d2*d2);
            bonds[tid] = bond; ems[tid] = em; colss[tid] = col;
        }
        __syncthreads();
        // --- stage 1: m1 = silu(cA + cB[col] + d*wd + bond*wb) ---
        #pragma unroll
        for (int rep = 0; rep < 4; ++rep) {
            int q = rep*256 + tid;
            int e = q >> 5;
            int k4 = (q & 31) << 2;
            int col = colss[e];
            const float* cb = (col >= NHY) ? (g_cBv + (b*NV + (col-NHY))*HD)
                                           : (g_cBh + (((b*NS+s)*NHY)+col)*HD);
            float4 cv = *(const float4*)(cb + k4);
            float dd = dists[e], bo = bonds[e];
            float4 o;
            o.x = silu_f(cAs[k4+0] + cv.x + dd*w1d[k4+0] + bo*w1b[k4+0]);
            o.y = silu_f(cAs[k4+1] + cv.y + dd*w1d[k4+1] + bo*w1b[k4+1]);
            o.z = silu_f(cAs[k4+2] + cv.z + dd*w1d[k4+2] + bo*w1b[k4+2]);
            o.w = silu_f(cAs[k4+3] + cv.w + dd*w1d[k4+3] + bo*w1b[k4+3]);
            *(float4*)(m1s + e*132 + k4) = o;
        }
        __syncthreads();
        int eg = tid & 7, cg = tid >> 3, c = cg*4;
        // --- stage 2: m2 = silu(m1@W2 + b2) * emask ---
        {
            float acc[16];
            #pragma unroll
            for (int u = 0; u < 4; ++u)
                for (int i = 0; i < 4; ++i) acc[u*4+i] = b2s[c+i];
            gemm4x4(m1s, eg, W2s, c, acc);
            #pragma unroll
            for (int u = 0; u < 4; ++u) {
                int e = eg + u*8;
                float em = ems[e];
                float4 v;
                v.x = silu_f(acc[u*4+0])*em; v.y = silu_f(acc[u*4+1])*em;
                v.z = silu_f(acc[u*4+2])*em; v.w = silu_f(acc[u*4+3])*em;
                *(float4*)(m2s + e*132 + c) = v;
            }
        }
        __syncthreads();
        // --- stage 3: cw = silu(m2@Wc1 + bc1) . Wc2 ---
        {
            float acc[16];
            #pragma unroll
            for (int u = 0; u < 4; ++u)
                for (int i = 0; i < 4; ++i) acc[u*4+i] = bc1s[c+i];
            gemm4x4(m2s, eg, Wc1s, c, acc);
            #pragma unroll
            for (int u = 0; u < 4; ++u) {
                int e = eg + u*8;
                float cw = 0.f;
                #pragma unroll
                for (int i = 0; i < 4; ++i) cw += silu_f(acc[u*4+i]) * wc2s[c+i];
                cwp[e*32+cg] = cw;
            }
        }
        __syncthreads();
        // --- stage 4a: aggregate m2, reduce cw partials ---
        if (tid < HD) {
            float a = aggm[tid];
            #pragma unroll
            for (int e = 0; e < 32; ++e) a += m2s[e*132+tid];
            aggm[tid] = a;
        } else if (tid < HD + 32) {
            int e = tid - HD;
            float sum = 0.f;
            #pragma unroll
            for (int i = 0; i < 32; ++i) sum += cwp[e*32+i];
            cws[e] = sum;
        }
        __syncthreads();
        // --- stage 4b: aggregate diff*cw ---
        if (tid < 3) {
            float a = aggx[tid];
            #pragma unroll
            for (int e = 0; e < 32; ++e) a += diffs[e*3+tid]*cws[e];
            aggx[tid] = a;
        }
        __syncthreads();
    }
    if (tid < HD) g_aggm[nidx*HD+tid] = aggm[tid];
    if (tid < 3)  g_aggx[nidx*3+tid]  = aggx[tid];
}

// ------------- node update -------------
__global__ void node_k(int l, const float* __restrict__ Wn1, const float* __restrict__ bn1,
                       const float* __restrict__ Wn2, const float* __restrict__ bn2) {
    __shared__ float ins[WN1R+1];
    __shared__ float hid[HD];
    int nidx = blockIdx.x;
    int tid = threadIdx.x;
    if (tid < FD) ins[tid] = g_feat[nidx*FD+tid];
    ins[FD+tid] = g_aggm[nidx*HD+tid];
    __syncthreads();
    const float* W = Wn1 + l*WN1R*HD;
    float h = bn1[l*HD+tid];
    #pragma unroll 4
    for (int i = 0; i < WN1R; ++i) h = fmaf(ins[i], W[i*HD+tid], h);
    hid[tid] = silu_f(h);
    __syncthreads();
    if (tid < FD) {
        const float* V = Wn2 + l*HD*FD;
        float o = bn2[l*FD+tid];
        #pragma unroll 4
        for (int k = 0; k < HD; ++k) o = fmaf(hid[k], V[k*FD+tid], o);
        g_feat[nidx*FD+tid] += o;
    }
    if (tid < 3) g_x[nidx*3+tid] += g_aggx[nidx*3+tid];
}

// ------------- output -------------
__global__ void final_k(const float* __restrict__ x_h, const float* __restrict__ x_hv,
                        const int* __restrict__ bound, const float* __restrict__ mask,
                        float* __restrict__ out) {
    int idx = blockIdx.x*blockDim.x + threadIdx.x;
    if (idx >= NNODE*3) return;
    int c = idx % 3;
    int n = idx / 3;
    int r = n % NHY;
    int b = n / (NHY*NS);
    int ba = bound[b*NHY+r];
    float x0 = x_h[idx] + x_hv[(b*NV+ba)*3+c];
    out[idx] = (g_x[idx] - x0) * mask[b*NHY+r];
}

extern "C" void kernel_launch(void* const* d_in, const int* in_sizes, int n_in,
                              void* d_out, int out_size) {
    const float* t     = (const float*)d_in[0];
    const float* x_h   = (const float*)d_in[1];
    const float* x_hv  = (const float*)d_in[2];
    const float* bondm = (const float*)d_in[3];
    const float* emhv  = (const float*)d_in[4];
    const float* emhh  = (const float*)d_in[5];
    const float* amask = (const float*)d_in[6];
    const float* W1    = (const float*)d_in[7];
    const float* b1    = (const float*)d_in[8];
    const float* W2    = (const float*)d_in[9];
    const float* b2    = (const float*)d_in[10];
    const float* Wc1   = (const float*)d_in[11];
    const float* bc1   = (const float*)d_in[12];
    const float* Wc2   = (const float*)d_in[13];
    const float* Wn1   = (const float*)d_in[14];
    const float* bn1   = (const float*)d_in[15];
    const float* Wn2   = (const float*)d_in[16];
    const float* bn2   = (const float*)d_in[17];
    const int* pept    = (const int*)d_in[18];
    const int* labv    = (const int*)d_in[19];
    const int* labh    = (const int*)d_in[20];
    const int* posv    = (const int*)d_in[21];
    const int* posh    = (const int*)d_in[22];
    const int* edges   = (const int*)d_in[23];
    const int* bound   = (const int*)d_in[24];
    float* out = (float*)d_out;

    cudaFuncSetAttribute(edge_k, cudaFuncAttributeMaxDynamicSharedMemorySize, EDGE_SMEM_BYTES);

    csr_k<<<NB, 64>>>(edges, emhh);
    init_k<<<(NNODE+127)/128, 128>>>(x_h, x_hv, bound, labh, posh, pept);
    for (int l = 0; l < NL; ++l) {
        heavycb_k<<<(NB*NV*HD+255)/256, 256>>>(l, W1, labv, posv, pept);
        hcab_k<<<NNODE, HD>>>(l, W1, b1, t);
        edge_k<<<NNODE, 256, EDGE_SMEM_BYTES>>>(l, W1, W2, b2, Wc1, bc1, Wc2,
                                                x_hv, bondm, emhv);
        node_k<<<NNODE, HD>>>(l, Wn1, bn1, Wn2, bn2);
    }
    final_k<<<(NNODE*3+127)/128, 128>>>(x_h, x_hv, bound, amask, out);
}